// round 11
// baseline (speedup 1.0000x reference)
#include <cuda_runtime.h>
#include <math.h>

typedef unsigned long long u64;

// ---------------------------------------------------------------------------
// Packed f32x2 helpers (Blackwell FFMA2 — only reachable via PTX fma.rn.f32x2)
// ---------------------------------------------------------------------------
__device__ __forceinline__ u64 pack2(float x) {
    u64 r; asm("mov.b64 %0, {%1, %1};" : "=l"(r) : "f"(x)); return r;
}
__device__ __forceinline__ void unpack2(u64 v, float& lo, float& hi) {
    asm("mov.b64 {%0, %1}, %2;" : "=f"(lo), "=f"(hi) : "l"(v));
}
__device__ __forceinline__ u64 fma2(u64 a, u64 b, u64 c) {
    u64 d; asm("fma.rn.f32x2 %0, %1, %2, %3;" : "=l"(d) : "l"(a), "l"(b), "l"(c));
    return d;
}

// ---------------------------------------------------------------------------
// Problem constants
// ---------------------------------------------------------------------------
#define IMG_H 1280
#define IMG_W 720
#define NH 64
#define NW 36
#define L_BLOCKS 2304
#define OUT_H 5120
#define OUT_W 2880
#define OUT_PLANE (OUT_H * OUT_W)
#define OUT_IMG (3 * OUT_PLANE)

#define G1_C 16
#define G1_H 640
#define G1_W 360
#define G1_AREA (G1_H * G1_W)
#define G2_C 8
#define G2_H 320
#define G2_W 180
#define G2_AREA (G2_H * G2_W)

__device__ float g_g1[G1_C * G1_AREA];
__device__ float g_g2[G2_C * G2_AREA];

// ---------------------------------------------------------------------------
// Kernel D: light expert. One CTA (96 threads) per 20x20 block.
// Item = 8 channels x 1x5 px. NEW mapping: thread's channel group is FIXED
// (cg = tid>>4); iteration `it` covers rows 4it..4it+3 for ALL channels ->
// each iteration's output is an exact [3][16][80] rectangle, staged in smem
// and written back with fully-coalesced cooperative float4 stores
// (~5 wavefronts/STG instr vs ~20 for the direct scattered stores).
// Weights loaded as LDS.128 (2x ulonglong2) -> half the weight instructions.
// ---------------------------------------------------------------------------
__global__ __launch_bounds__(96)
void light_kernel(const float* __restrict__ in,
                  const float* __restrict__ wl,
                  const float* __restrict__ bl,
                  float* __restrict__ out)
{
    __shared__ u64  s_in2[3][22][36];            // duplicated input, stride 36 u64
    __shared__ float s_wT[27][48];               // [k-position][out channel]
    __shared__ float s_b[48];
    __shared__ __align__(16) float s_out[3][16][84];  // iteration output stage

    const int tid = threadIdx.x;
    const int blk = blockIdx.x;
    const int bh = blk / NW;
    const int bw = blk % NW;

    for (int i = tid; i < 27 * 48; i += 96) {
        int k = i / 48, oc = i % 48;
        s_wT[k][oc] = wl[oc * 27 + k];
    }
    if (tid < 48) s_b[tid] = bl[tid];

    for (int i = tid; i < 3 * 22 * 22; i += 96) {
        int x = i % 22;
        int y = (i / 22) % 22;
        int c = i / 484;
        float v = 0.0f;
        if (y >= 1 && y <= 20 && x >= 1 && x <= 20)
            v = in[c * (IMG_H * IMG_W) + (bh * 20 + y - 1) * IMG_W + (bw * 20 + x - 1)];
        s_in2[c][y][x] = pack2(v);
    }

    // Per-thread invariants (channel group fixed across iterations)
    const int cg     = tid >> 4;          // 0..5
    const int lane16 = tid & 15;
    const int oc0    = cg * 8;
    const int c_img  = cg >> 1;
    const int r1a    = (cg & 1) * 2;
    const int q0     = (lane16 & 3) * 5;  // col group -> 5 cols
    const int prow   = lane16 >> 2;       // 0..3, + 4*it below

    __syncthreads();

    #pragma unroll 1
    for (int it = 0; it < 5; it++) {
        const int p = prow + 4 * it;      // row 0..19

        u64 acc[5][4];
        {
            u64 b0 = *(const u64*)&s_b[oc0 + 0];
            u64 b1 = *(const u64*)&s_b[oc0 + 2];
            u64 b2 = *(const u64*)&s_b[oc0 + 4];
            u64 b3 = *(const u64*)&s_b[oc0 + 6];
            #pragma unroll
            for (int j = 0; j < 5; j++) {
                acc[j][0] = b0; acc[j][1] = b1;
                acc[j][2] = b2; acc[j][3] = b3;
            }
        }

        #pragma unroll
        for (int ic = 0; ic < 3; ic++) {
            #pragma unroll
            for (int kh = 0; kh < 3; kh++) {
                u64 xx[7];
                #pragma unroll
                for (int c = 0; c < 7; c++)
                    xx[c] = s_in2[ic][p + kh][q0 + c];
                #pragma unroll
                for (int kw = 0; kw < 3; kw++) {
                    const float* wp = &s_wT[ic * 9 + kh * 3 + kw][oc0];
                    ulonglong2 wA = *(const ulonglong2*)(wp);      // w0,w1 (LDS.128)
                    ulonglong2 wB = *(const ulonglong2*)(wp + 4);  // w2,w3 (LDS.128)
                    #pragma unroll
                    for (int j = 0; j < 5; j++) {
                        u64 x = xx[j + kw];
                        acc[j][0] = fma2(x, wA.x, acc[j][0]);
                        acc[j][1] = fma2(x, wA.y, acc[j][1]);
                        acc[j][2] = fma2(x, wB.x, acc[j][2]);
                        acc[j][3] = fma2(x, wB.y, acc[j][3]);
                    }
                }
            }
        }

        // Stage into smem rectangle [c_img][lr][col]
        const int lr = ((p & 3) << 2) + r1a;
        #pragma unroll
        for (int j = 0; j < 5; j++) {
            int col = (q0 + j) * 4;
            float4 v;
            unpack2(acc[j][0], v.x, v.y);
            unpack2(acc[j][1], v.z, v.w);
            v.x = fminf(fmaxf(v.x, 0.0f), 0.6f) + 0.4f;
            v.y = fminf(fmaxf(v.y, 0.0f), 0.6f) + 0.4f;
            v.z = fminf(fmaxf(v.z, 0.0f), 0.6f) + 0.4f;
            v.w = fminf(fmaxf(v.w, 0.0f), 0.6f) + 0.4f;
            *(float4*)&s_out[c_img][lr][col] = v;

            unpack2(acc[j][2], v.x, v.y);
            unpack2(acc[j][3], v.z, v.w);
            v.x = fminf(fmaxf(v.x, 0.0f), 0.6f) + 0.4f;
            v.y = fminf(fmaxf(v.y, 0.0f), 0.6f) + 0.4f;
            v.z = fminf(fmaxf(v.z, 0.0f), 0.6f) + 0.4f;
            v.w = fminf(fmaxf(v.w, 0.0f), 0.6f) + 0.4f;
            *(float4*)&s_out[c_img][lr + 1][col] = v;
        }
        __syncthreads();

        // Cooperative coalesced store: 960 float4s, 10 per thread
        #pragma unroll
        for (int n = 0; n < 10; n++) {
            int f  = n * 96 + tid;
            int c  = f / 320;
            int rm = f - c * 320;
            int r  = rm / 20;
            int q4 = rm - r * 20;
            float4 v = *(const float4*)&s_out[c][r][q4 * 4];
            *(float4*)&out[(size_t)c * OUT_PLANE
                         + (size_t)(bh * 80 + 16 * it + r) * OUT_W
                         + (bw * 80 + q4 * 4)] = v;
        }
        __syncthreads();
    }
}

// ---------------------------------------------------------------------------
// Kernel A: gate conv1 + maxpool2 + tanh (swapped: tanh monotone) -> g1
// 64-thread CTAs, 8x8 pooled tile.
// ---------------------------------------------------------------------------
__global__ __launch_bounds__(64)
void gate1_kernel(const float* __restrict__ in,
                  const float* __restrict__ w1,
                  const float* __restrict__ b1)
{
    __shared__ u64  s_in2[3][18][19];
    __shared__ float s_wT[27][16];
    __shared__ float s_b[16];

    const int tid = threadIdx.x;
    const int tx = tid & 7, ty = tid >> 3;
    const int ty0 = blockIdx.y * 8;
    const int tx0 = blockIdx.x * 8;

    for (int i = tid; i < 27 * 16; i += 64) {
        int k = i >> 4, oc = i & 15;
        s_wT[k][oc] = w1[oc * 27 + k];
    }
    if (tid < 16) s_b[tid] = b1[tid];

    for (int i = tid; i < 3 * 18 * 18; i += 64) {
        int x = i % 18;
        int y = (i / 18) % 18;
        int c = i / 324;
        int gy = min(max(ty0 * 2 - 1 + y, 0), IMG_H - 1);
        int gx = min(max(tx0 * 2 - 1 + x, 0), IMG_W - 1);
        s_in2[c][y][x] = pack2(in[c * (IMG_H * IMG_W) + gy * IMG_W + gx]);
    }
    __syncthreads();

    u64 acc[2][2][8];
    {
        #pragma unroll
        for (int m = 0; m < 8; m++) {
            u64 b = *(const u64*)&s_b[2 * m];
            acc[0][0][m] = b; acc[0][1][m] = b;
            acc[1][0][m] = b; acc[1][1][m] = b;
        }
    }

    #pragma unroll
    for (int ic = 0; ic < 3; ic++) {
        #pragma unroll
        for (int kh = 0; kh < 3; kh++) {
            u64 xx[2][4];
            #pragma unroll
            for (int dy = 0; dy < 2; dy++)
                #pragma unroll
                for (int c = 0; c < 4; c++)
                    xx[dy][c] = s_in2[ic][2 * ty + kh + dy][2 * tx + c];
            #pragma unroll
            for (int kw = 0; kw < 3; kw++) {
                const float* wp = &s_wT[ic * 9 + kh * 3 + kw][0];
                u64 w[8];
                #pragma unroll
                for (int m = 0; m < 8; m++) w[m] = *(const u64*)(wp + 2 * m);
                #pragma unroll
                for (int dy = 0; dy < 2; dy++)
                    #pragma unroll
                    for (int dx = 0; dx < 2; dx++) {
                        u64 x = xx[dy][dx + kw];
                        #pragma unroll
                        for (int m = 0; m < 8; m++)
                            acc[dy][dx][m] = fma2(x, w[m], acc[dy][dx][m]);
                    }
            }
        }
    }

    int py = ty0 + ty;
    int px = tx0 + tx;
    if (py < G1_H && px < G1_W) {
        #pragma unroll
        for (int m = 0; m < 8; m++) {
            float m0 = -1e30f, m1 = -1e30f;
            #pragma unroll
            for (int dy = 0; dy < 2; dy++)
                #pragma unroll
                for (int dx = 0; dx < 2; dx++) {
                    float lo, hi;
                    unpack2(acc[dy][dx][m], lo, hi);
                    m0 = fmaxf(m0, lo);
                    m1 = fmaxf(m1, hi);
                }
            g_g1[(2 * m + 0) * G1_AREA + py * G1_W + px] = tanhf(m0);
            g_g1[(2 * m + 1) * G1_AREA + py * G1_W + px] = tanhf(m1);
        }
    }
}

// ---------------------------------------------------------------------------
// Kernel B: gate conv2 + maxpool2 -> g2. 8x8 pooled tile per 64-thread CTA.
// ---------------------------------------------------------------------------
__global__ __launch_bounds__(64)
void gate2_kernel(const float* __restrict__ w2,
                  const float* __restrict__ b2)
{
    __shared__ float s_g[16][18][19];
    __shared__ float s_wT[144][8];

    const int tid = threadIdx.x;
    const int tx = tid & 7, ty = tid >> 3;
    const int ty0 = blockIdx.y * 8;
    const int tx0 = blockIdx.x * 8;

    for (int i = tid; i < 144 * 8; i += 64) {
        int k = i >> 3, oc = i & 7;
        s_wT[k][oc] = w2[oc * 144 + k];
    }

    for (int i = tid; i < 16 * 18 * 18; i += 64) {
        int x = i % 18;
        int y = (i / 18) % 18;
        int c = i / 324;
        int gy = min(max(ty0 * 2 - 1 + y, 0), G1_H - 1);
        int gx = min(max(tx0 * 2 - 1 + x, 0), G1_W - 1);
        s_g[c][y][x] = g_g1[c * G1_AREA + gy * G1_W + gx];
    }
    __syncthreads();

    u64 acc[2][2][4];
    u64 z = pack2(0.0f);
    #pragma unroll
    for (int dy = 0; dy < 2; dy++)
        #pragma unroll
        for (int dx = 0; dx < 2; dx++)
            #pragma unroll
            for (int m = 0; m < 4; m++) acc[dy][dx][m] = z;

    #pragma unroll 1
    for (int ic = 0; ic < 16; ic++) {
        #pragma unroll
        for (int kh = 0; kh < 3; kh++) {
            u64 xx[2][4];
            #pragma unroll
            for (int dy = 0; dy < 2; dy++)
                #pragma unroll
                for (int c = 0; c < 4; c++)
                    xx[dy][c] = pack2(s_g[ic][2 * ty + kh + dy][2 * tx + c]);
            #pragma unroll
            for (int kw = 0; kw < 3; kw++) {
                const float* wp = &s_wT[ic * 9 + kh * 3 + kw][0];
                u64 w0 = *(const u64*)(wp + 0);
                u64 w1 = *(const u64*)(wp + 2);
                u64 w2p = *(const u64*)(wp + 4);
                u64 w3 = *(const u64*)(wp + 6);
                #pragma unroll
                for (int dy = 0; dy < 2; dy++)
                    #pragma unroll
                    for (int dx = 0; dx < 2; dx++) {
                        u64 x = xx[dy][dx + kw];
                        acc[dy][dx][0] = fma2(x, w0, acc[dy][dx][0]);
                        acc[dy][dx][1] = fma2(x, w1, acc[dy][dx][1]);
                        acc[dy][dx][2] = fma2(x, w2p, acc[dy][dx][2]);
                        acc[dy][dx][3] = fma2(x, w3, acc[dy][dx][3]);
                    }
            }
        }
    }

    int py = ty0 + ty;
    int px = tx0 + tx;
    if (py < G2_H && px < G2_W) {
        #pragma unroll
        for (int m = 0; m < 4; m++) {
            float m0 = -1e30f, m1 = -1e30f;
            #pragma unroll
            for (int dy = 0; dy < 2; dy++)
                #pragma unroll
                for (int dx = 0; dx < 2; dx++) {
                    float lo, hi;
                    unpack2(acc[dy][dx][m], lo, hi);
                    m0 = fmaxf(m0, lo);
                    m1 = fmaxf(m1, hi);
                }
            g_g2[(2 * m + 0) * G2_AREA + py * G2_W + px] = m0 + b2[2 * m + 0];
            g_g2[(2 * m + 1) * G2_AREA + py * G2_W + px] = m1 + b2[2 * m + 1];
        }
    }
}

// ---------------------------------------------------------------------------
// Kernel C: gate conv3 (5x5 stride 5) + sigmoid. One warp per output.
// ---------------------------------------------------------------------------
__global__ __launch_bounds__(256)
void gate3_kernel(const float* __restrict__ w3,
                  const float* __restrict__ b3,
                  float* __restrict__ out_cv)
{
    __shared__ float s_w[200];
    int tid = threadIdx.x;
    if (tid < 200) s_w[tid] = w3[tid];
    __syncthreads();

    int lane = tid & 31;
    int o = blockIdx.x * 8 + (tid >> 5);
    if (o >= L_BLOCKS) return;
    int by = o / NW;
    int bx = o % NW;

    float v = 0.0f;
    if (lane < 25) {
        int ky = lane / 5, kx = lane % 5;
        const float* gp = &g_g2[(by * 5 + ky) * G2_W + (bx * 5 + kx)];
        #pragma unroll
        for (int ic = 0; ic < 8; ic++)
            v = fmaf(gp[ic * G2_AREA], s_w[ic * 25 + lane], v);
    }

    v += __shfl_xor_sync(0xffffffffu, v, 16);
    v += __shfl_xor_sync(0xffffffffu, v, 8);
    v += __shfl_xor_sync(0xffffffffu, v, 4);
    v += __shfl_xor_sync(0xffffffffu, v, 2);
    v += __shfl_xor_sync(0xffffffffu, v, 1);

    if (lane == 0)
        out_cv[o] = 1.0f / (1.0f + expf(-(v + b3[0])));
}

// ---------------------------------------------------------------------------
// Launch: gate chain forked onto a side stream, overlapped with light.
// ---------------------------------------------------------------------------
static cudaStream_t g_sG = 0;
static cudaEvent_t  g_evFork = 0, g_evJoin = 0;

extern "C" void kernel_launch(void* const* d_in, const int* in_sizes, int n_in,
                              void* d_out, int out_size)
{
    const float* in = (const float*)d_in[0];
    const float* w1 = (const float*)d_in[1];
    const float* b1 = (const float*)d_in[2];
    const float* w2 = (const float*)d_in[3];
    const float* b2 = (const float*)d_in[4];
    const float* w3 = (const float*)d_in[5];
    const float* b3 = (const float*)d_in[6];
    const float* wl = (const float*)d_in[7];
    const float* bl = (const float*)d_in[8];
    // complex expert weights (d_in[9..14]) are provably dead: sigmoid(x) > 1 never

    float* out = (float*)d_out;

    if (g_sG == 0) {
        cudaStreamCreateWithFlags(&g_sG, cudaStreamNonBlocking);
        cudaEventCreateWithFlags(&g_evFork, cudaEventDisableTiming);
        cudaEventCreateWithFlags(&g_evJoin, cudaEventDisableTiming);
    }

    // Fork: gate chain on side stream
    cudaEventRecord(g_evFork, 0);
    cudaStreamWaitEvent(g_sG, g_evFork, 0);
    gate1_kernel<<<dim3((G1_W + 7) / 8, (G1_H + 7) / 8), 64, 0, g_sG>>>(in, w1, b1);
    gate2_kernel<<<dim3((G2_W + 7) / 8, (G2_H + 7) / 8), 64, 0, g_sG>>>(w2, b2);
    gate3_kernel<<<L_BLOCKS / 8, 256, 0, g_sG>>>(w3, b3, out + OUT_IMG);
    cudaEventRecord(g_evJoin, g_sG);

    // Main stream: light expert (dominant, overlaps the gate chain)
    light_kernel<<<L_BLOCKS, 96>>>(in, wl, bl, out);

    // Join
    cudaStreamWaitEvent(0, g_evJoin, 0);
}

// round 12
// speedup vs baseline: 1.1550x; 1.1550x over previous
#include <cuda_runtime.h>
#include <math.h>

typedef unsigned long long u64;

// ---------------------------------------------------------------------------
// Packed f32x2 helpers (Blackwell FFMA2 — only reachable via PTX fma.rn.f32x2)
// ---------------------------------------------------------------------------
__device__ __forceinline__ u64 pack2(float x) {
    u64 r; asm("mov.b64 %0, {%1, %1};" : "=l"(r) : "f"(x)); return r;
}
__device__ __forceinline__ void unpack2(u64 v, float& lo, float& hi) {
    asm("mov.b64 {%0, %1}, %2;" : "=f"(lo), "=f"(hi) : "l"(v));
}
__device__ __forceinline__ u64 fma2(u64 a, u64 b, u64 c) {
    u64 d; asm("fma.rn.f32x2 %0, %1, %2, %3;" : "=l"(d) : "l"(a), "l"(b), "l"(c));
    return d;
}

// ---------------------------------------------------------------------------
// Problem constants
// ---------------------------------------------------------------------------
#define IMG_H 1280
#define IMG_W 720
#define NH 64
#define NW 36
#define L_BLOCKS 2304
#define OUT_H 5120
#define OUT_W 2880
#define OUT_PLANE (OUT_H * OUT_W)
#define OUT_IMG (3 * OUT_PLANE)

#define G1_C 16
#define G1_H 640
#define G1_W 360
#define G1_AREA (G1_H * G1_W)
#define G2_C 8
#define G2_H 320
#define G2_W 180
#define G2_AREA (G2_H * G2_W)

__device__ float g_g1[G1_C * G1_AREA];
__device__ float g_g2[G2_C * G2_AREA];

// ---------------------------------------------------------------------------
// Kernel D: light expert. EXACT R10 structure (best known: 81us, 72 regs,
// 7 CTAs/SM) with ONE change: weights loaded as LDS.128 (2x ulonglong2)
// instead of 4x LDS.64 -> 54 fewer LDS instructions and ~108 fewer L1
// wavefronts per warp-loop, at zero register/smem cost.
// Input tile stride 36 u64: bank index (4p+5Q) mod 16 is a perfect 16-cover
// per half-warp -> conflict-free LDS.64. No min-blocks hint (R5/R9 lesson).
// ---------------------------------------------------------------------------
__global__ __launch_bounds__(96)
void light_kernel(const float* __restrict__ in,
                  const float* __restrict__ wl,
                  const float* __restrict__ bl,
                  float* __restrict__ out)
{
    __shared__ u64  s_in2[3][22][36];   // duplicated input, row stride 36 u64
    __shared__ __align__(16) float s_wT[27][48];  // [k-position][out channel]
    __shared__ float s_b[48];

    const int tid = threadIdx.x;
    const int blk = blockIdx.x;
    const int bh = blk / NW;
    const int bw = blk % NW;

    for (int i = tid; i < 27 * 48; i += 96) {
        int k = i / 48, oc = i % 48;
        s_wT[k][oc] = wl[oc * 27 + k];
    }
    if (tid < 48) s_b[tid] = bl[tid];

    for (int i = tid; i < 3 * 22 * 22; i += 96) {
        int x = i % 22;
        int y = (i / 22) % 22;
        int c = i / 484;
        float v = 0.0f;
        if (y >= 1 && y <= 20 && x >= 1 && x <= 20)
            v = in[c * (IMG_H * IMG_W) + (bh * 20 + y - 1) * IMG_W + (bw * 20 + x - 1)];
        s_in2[c][y][x] = pack2(v);
    }
    __syncthreads();

    #pragma unroll 1
    for (int it = 0; it < 5; it++) {
        const int item = tid + 96 * it;      // 0..479
        const int cg  = item / 80;           // 6 channel groups of 8
        const int rem = item % 80;
        const int p   = rem >> 2;            // row 0..19
        const int q0  = (rem & 3) * 5;       // col group -> 5 cols
        const int oc0 = cg * 8;
        const int c_img = oc0 >> 4;
        const int r1a = (oc0 & 15) >> 2;

        u64 acc[5][4];
        {
            u64 b0 = *(const u64*)&s_b[oc0 + 0];
            u64 b1 = *(const u64*)&s_b[oc0 + 2];
            u64 b2 = *(const u64*)&s_b[oc0 + 4];
            u64 b3 = *(const u64*)&s_b[oc0 + 6];
            #pragma unroll
            for (int j = 0; j < 5; j++) {
                acc[j][0] = b0; acc[j][1] = b1;
                acc[j][2] = b2; acc[j][3] = b3;
            }
        }

        #pragma unroll
        for (int ic = 0; ic < 3; ic++) {
            #pragma unroll
            for (int kh = 0; kh < 3; kh++) {
                u64 xx[7];
                #pragma unroll
                for (int c = 0; c < 7; c++)
                    xx[c] = s_in2[ic][p + kh][q0 + c];
                #pragma unroll
                for (int kw = 0; kw < 3; kw++) {
                    const float* wp = &s_wT[ic * 9 + kh * 3 + kw][oc0];
                    ulonglong2 wA = *(const ulonglong2*)(wp);      // LDS.128: w0,w1
                    ulonglong2 wB = *(const ulonglong2*)(wp + 4);  // LDS.128: w2,w3
                    #pragma unroll
                    for (int j = 0; j < 5; j++) {
                        u64 x = xx[j + kw];
                        acc[j][0] = fma2(x, wA.x, acc[j][0]);
                        acc[j][1] = fma2(x, wA.y, acc[j][1]);
                        acc[j][2] = fma2(x, wB.x, acc[j][2]);
                        acc[j][3] = fma2(x, wB.y, acc[j][3]);
                    }
                }
            }
        }

        #pragma unroll
        for (int j = 0; j < 5; j++) {
            int q = q0 + j;
            size_t base = (size_t)c_img * OUT_PLANE
                        + (size_t)(bh * 80 + p * 4 + r1a) * OUT_W
                        + (bw * 80 + q * 4);
            float4 v;
            unpack2(acc[j][0], v.x, v.y);
            unpack2(acc[j][1], v.z, v.w);
            v.x = fminf(fmaxf(v.x, 0.0f), 0.6f) + 0.4f;
            v.y = fminf(fmaxf(v.y, 0.0f), 0.6f) + 0.4f;
            v.z = fminf(fmaxf(v.z, 0.0f), 0.6f) + 0.4f;
            v.w = fminf(fmaxf(v.w, 0.0f), 0.6f) + 0.4f;
            *reinterpret_cast<float4*>(&out[base]) = v;

            unpack2(acc[j][2], v.x, v.y);
            unpack2(acc[j][3], v.z, v.w);
            v.x = fminf(fmaxf(v.x, 0.0f), 0.6f) + 0.4f;
            v.y = fminf(fmaxf(v.y, 0.0f), 0.6f) + 0.4f;
            v.z = fminf(fmaxf(v.z, 0.0f), 0.6f) + 0.4f;
            v.w = fminf(fmaxf(v.w, 0.0f), 0.6f) + 0.4f;
            *reinterpret_cast<float4*>(&out[base + OUT_W]) = v;
        }
    }
}

// ---------------------------------------------------------------------------
// Kernel A: gate conv1 + maxpool2 + tanh (swapped: tanh monotone) -> g1
// 64-thread CTAs, 8x8 pooled tile.
// ---------------------------------------------------------------------------
__global__ __launch_bounds__(64)
void gate1_kernel(const float* __restrict__ in,
                  const float* __restrict__ w1,
                  const float* __restrict__ b1)
{
    __shared__ u64  s_in2[3][18][19];
    __shared__ float s_wT[27][16];
    __shared__ float s_b[16];

    const int tid = threadIdx.x;
    const int tx = tid & 7, ty = tid >> 3;
    const int ty0 = blockIdx.y * 8;
    const int tx0 = blockIdx.x * 8;

    for (int i = tid; i < 27 * 16; i += 64) {
        int k = i >> 4, oc = i & 15;
        s_wT[k][oc] = w1[oc * 27 + k];
    }
    if (tid < 16) s_b[tid] = b1[tid];

    for (int i = tid; i < 3 * 18 * 18; i += 64) {
        int x = i % 18;
        int y = (i / 18) % 18;
        int c = i / 324;
        int gy = min(max(ty0 * 2 - 1 + y, 0), IMG_H - 1);
        int gx = min(max(tx0 * 2 - 1 + x, 0), IMG_W - 1);
        s_in2[c][y][x] = pack2(in[c * (IMG_H * IMG_W) + gy * IMG_W + gx]);
    }
    __syncthreads();

    u64 acc[2][2][8];
    {
        #pragma unroll
        for (int m = 0; m < 8; m++) {
            u64 b = *(const u64*)&s_b[2 * m];
            acc[0][0][m] = b; acc[0][1][m] = b;
            acc[1][0][m] = b; acc[1][1][m] = b;
        }
    }

    #pragma unroll
    for (int ic = 0; ic < 3; ic++) {
        #pragma unroll
        for (int kh = 0; kh < 3; kh++) {
            u64 xx[2][4];
            #pragma unroll
            for (int dy = 0; dy < 2; dy++)
                #pragma unroll
                for (int c = 0; c < 4; c++)
                    xx[dy][c] = s_in2[ic][2 * ty + kh + dy][2 * tx + c];
            #pragma unroll
            for (int kw = 0; kw < 3; kw++) {
                const float* wp = &s_wT[ic * 9 + kh * 3 + kw][0];
                u64 w[8];
                #pragma unroll
                for (int m = 0; m < 8; m++) w[m] = *(const u64*)(wp + 2 * m);
                #pragma unroll
                for (int dy = 0; dy < 2; dy++)
                    #pragma unroll
                    for (int dx = 0; dx < 2; dx++) {
                        u64 x = xx[dy][dx + kw];
                        #pragma unroll
                        for (int m = 0; m < 8; m++)
                            acc[dy][dx][m] = fma2(x, w[m], acc[dy][dx][m]);
                    }
            }
        }
    }

    int py = ty0 + ty;
    int px = tx0 + tx;
    if (py < G1_H && px < G1_W) {
        #pragma unroll
        for (int m = 0; m < 8; m++) {
            float m0 = -1e30f, m1 = -1e30f;
            #pragma unroll
            for (int dy = 0; dy < 2; dy++)
                #pragma unroll
                for (int dx = 0; dx < 2; dx++) {
                    float lo, hi;
                    unpack2(acc[dy][dx][m], lo, hi);
                    m0 = fmaxf(m0, lo);
                    m1 = fmaxf(m1, hi);
                }
            g_g1[(2 * m + 0) * G1_AREA + py * G1_W + px] = tanhf(m0);
            g_g1[(2 * m + 1) * G1_AREA + py * G1_W + px] = tanhf(m1);
        }
    }
}

// ---------------------------------------------------------------------------
// Kernel B: gate conv2 + maxpool2 -> g2. 8x8 pooled tile per 64-thread CTA.
// ---------------------------------------------------------------------------
__global__ __launch_bounds__(64)
void gate2_kernel(const float* __restrict__ w2,
                  const float* __restrict__ b2)
{
    __shared__ float s_g[16][18][19];
    __shared__ float s_wT[144][8];

    const int tid = threadIdx.x;
    const int tx = tid & 7, ty = tid >> 3;
    const int ty0 = blockIdx.y * 8;
    const int tx0 = blockIdx.x * 8;

    for (int i = tid; i < 144 * 8; i += 64) {
        int k = i >> 3, oc = i & 7;
        s_wT[k][oc] = w2[oc * 144 + k];
    }

    for (int i = tid; i < 16 * 18 * 18; i += 64) {
        int x = i % 18;
        int y = (i / 18) % 18;
        int c = i / 324;
        int gy = min(max(ty0 * 2 - 1 + y, 0), G1_H - 1);
        int gx = min(max(tx0 * 2 - 1 + x, 0), G1_W - 1);
        s_g[c][y][x] = g_g1[c * G1_AREA + gy * G1_W + gx];
    }
    __syncthreads();

    u64 acc[2][2][4];
    u64 z = pack2(0.0f);
    #pragma unroll
    for (int dy = 0; dy < 2; dy++)
        #pragma unroll
        for (int dx = 0; dx < 2; dx++)
            #pragma unroll
            for (int m = 0; m < 4; m++) acc[dy][dx][m] = z;

    #pragma unroll 1
    for (int ic = 0; ic < 16; ic++) {
        #pragma unroll
        for (int kh = 0; kh < 3; kh++) {
            u64 xx[2][4];
            #pragma unroll
            for (int dy = 0; dy < 2; dy++)
                #pragma unroll
                for (int c = 0; c < 4; c++)
                    xx[dy][c] = pack2(s_g[ic][2 * ty + kh + dy][2 * tx + c]);
            #pragma unroll
            for (int kw = 0; kw < 3; kw++) {
                const float* wp = &s_wT[ic * 9 + kh * 3 + kw][0];
                u64 w0 = *(const u64*)(wp + 0);
                u64 w1 = *(const u64*)(wp + 2);
                u64 w2p = *(const u64*)(wp + 4);
                u64 w3 = *(const u64*)(wp + 6);
                #pragma unroll
                for (int dy = 0; dy < 2; dy++)
                    #pragma unroll
                    for (int dx = 0; dx < 2; dx++) {
                        u64 x = xx[dy][dx + kw];
                        acc[dy][dx][0] = fma2(x, w0, acc[dy][dx][0]);
                        acc[dy][dx][1] = fma2(x, w1, acc[dy][dx][1]);
                        acc[dy][dx][2] = fma2(x, w2p, acc[dy][dx][2]);
                        acc[dy][dx][3] = fma2(x, w3, acc[dy][dx][3]);
                    }
            }
        }
    }

    int py = ty0 + ty;
    int px = tx0 + tx;
    if (py < G2_H && px < G2_W) {
        #pragma unroll
        for (int m = 0; m < 4; m++) {
            float m0 = -1e30f, m1 = -1e30f;
            #pragma unroll
            for (int dy = 0; dy < 2; dy++)
                #pragma unroll
                for (int dx = 0; dx < 2; dx++) {
                    float lo, hi;
                    unpack2(acc[dy][dx][m], lo, hi);
                    m0 = fmaxf(m0, lo);
                    m1 = fmaxf(m1, hi);
                }
            g_g2[(2 * m + 0) * G2_AREA + py * G2_W + px] = m0 + b2[2 * m + 0];
            g_g2[(2 * m + 1) * G2_AREA + py * G2_W + px] = m1 + b2[2 * m + 1];
        }
    }
}

// ---------------------------------------------------------------------------
// Kernel C: gate conv3 (5x5 stride 5) + sigmoid. One warp per output.
// ---------------------------------------------------------------------------
__global__ __launch_bounds__(256)
void gate3_kernel(const float* __restrict__ w3,
                  const float* __restrict__ b3,
                  float* __restrict__ out_cv)
{
    __shared__ float s_w[200];
    int tid = threadIdx.x;
    if (tid < 200) s_w[tid] = w3[tid];
    __syncthreads();

    int lane = tid & 31;
    int o = blockIdx.x * 8 + (tid >> 5);
    if (o >= L_BLOCKS) return;
    int by = o / NW;
    int bx = o % NW;

    float v = 0.0f;
    if (lane < 25) {
        int ky = lane / 5, kx = lane % 5;
        const float* gp = &g_g2[(by * 5 + ky) * G2_W + (bx * 5 + kx)];
        #pragma unroll
        for (int ic = 0; ic < 8; ic++)
            v = fmaf(gp[ic * G2_AREA], s_w[ic * 25 + lane], v);
    }

    v += __shfl_xor_sync(0xffffffffu, v, 16);
    v += __shfl_xor_sync(0xffffffffu, v, 8);
    v += __shfl_xor_sync(0xffffffffu, v, 4);
    v += __shfl_xor_sync(0xffffffffu, v, 2);
    v += __shfl_xor_sync(0xffffffffu, v, 1);

    if (lane == 0)
        out_cv[o] = 1.0f / (1.0f + expf(-(v + b3[0])));
}

// ---------------------------------------------------------------------------
// Launch: gate chain forked onto a side stream, overlapped with light.
// ---------------------------------------------------------------------------
static cudaStream_t g_sG = 0;
static cudaEvent_t  g_evFork = 0, g_evJoin = 0;

extern "C" void kernel_launch(void* const* d_in, const int* in_sizes, int n_in,
                              void* d_out, int out_size)
{
    const float* in = (const float*)d_in[0];
    const float* w1 = (const float*)d_in[1];
    const float* b1 = (const float*)d_in[2];
    const float* w2 = (const float*)d_in[3];
    const float* b2 = (const float*)d_in[4];
    const float* w3 = (const float*)d_in[5];
    const float* b3 = (const float*)d_in[6];
    const float* wl = (const float*)d_in[7];
    const float* bl = (const float*)d_in[8];
    // complex expert weights (d_in[9..14]) are provably dead: sigmoid(x) > 1 never

    float* out = (float*)d_out;

    if (g_sG == 0) {
        cudaStreamCreateWithFlags(&g_sG, cudaStreamNonBlocking);
        cudaEventCreateWithFlags(&g_evFork, cudaEventDisableTiming);
        cudaEventCreateWithFlags(&g_evJoin, cudaEventDisableTiming);
    }

    // Fork: gate chain on side stream
    cudaEventRecord(g_evFork, 0);
    cudaStreamWaitEvent(g_sG, g_evFork, 0);
    gate1_kernel<<<dim3((G1_W + 7) / 8, (G1_H + 7) / 8), 64, 0, g_sG>>>(in, w1, b1);
    gate2_kernel<<<dim3((G2_W + 7) / 8, (G2_H + 7) / 8), 64, 0, g_sG>>>(w2, b2);
    gate3_kernel<<<L_BLOCKS / 8, 256, 0, g_sG>>>(w3, b3, out + OUT_IMG);
    cudaEventRecord(g_evJoin, g_sG);

    // Main stream: light expert (dominant, overlaps the gate chain)
    light_kernel<<<L_BLOCKS, 96>>>(in, wl, bl, out);

    // Join
    cudaStreamWaitEvent(0, g_evJoin, 0);
}

// round 13
// speedup vs baseline: 1.1620x; 1.0061x over previous
#include <cuda_runtime.h>
#include <math.h>

typedef unsigned long long u64;

// ---------------------------------------------------------------------------
// Packed f32x2 helpers (Blackwell FFMA2 — only reachable via PTX fma.rn.f32x2)
// ---------------------------------------------------------------------------
__device__ __forceinline__ u64 pack2(float x) {
    u64 r; asm("mov.b64 %0, {%1, %1};" : "=l"(r) : "f"(x)); return r;
}
__device__ __forceinline__ void unpack2(u64 v, float& lo, float& hi) {
    asm("mov.b64 {%0, %1}, %2;" : "=f"(lo), "=f"(hi) : "l"(v));
}
__device__ __forceinline__ u64 fma2(u64 a, u64 b, u64 c) {
    u64 d; asm("fma.rn.f32x2 %0, %1, %2, %3;" : "=l"(d) : "l"(a), "l"(b), "l"(c));
    return d;
}

// ---------------------------------------------------------------------------
// Problem constants
// ---------------------------------------------------------------------------
#define IMG_H 1280
#define IMG_W 720
#define NH 64
#define NW 36
#define L_BLOCKS 2304
#define OUT_H 5120
#define OUT_W 2880
#define OUT_PLANE (OUT_H * OUT_W)
#define OUT_IMG (3 * OUT_PLANE)

#define G1_C 16
#define G1_H 640
#define G1_W 360
#define G1_AREA (G1_H * G1_W)
#define G2_C 8
#define G2_H 320
#define G2_W 180
#define G2_AREA (G2_H * G2_W)

__device__ float g_g1[G1_C * G1_AREA];
__device__ float g_g2[G2_C * G2_AREA];

// ---------------------------------------------------------------------------
// Kernel D: light expert (byte-identical to R12 best: 79.8us, 72 regs,
// 7 CTAs/SM, conflict-free stride-36 tile, LDS.128 weights).
// ---------------------------------------------------------------------------
__global__ __launch_bounds__(96)
void light_kernel(const float* __restrict__ in,
                  const float* __restrict__ wl,
                  const float* __restrict__ bl,
                  float* __restrict__ out)
{
    __shared__ u64  s_in2[3][22][36];   // duplicated input, row stride 36 u64
    __shared__ __align__(16) float s_wT[27][48];  // [k-position][out channel]
    __shared__ float s_b[48];

    const int tid = threadIdx.x;
    const int blk = blockIdx.x;
    const int bh = blk / NW;
    const int bw = blk % NW;

    for (int i = tid; i < 27 * 48; i += 96) {
        int k = i / 48, oc = i % 48;
        s_wT[k][oc] = wl[oc * 27 + k];
    }
    if (tid < 48) s_b[tid] = bl[tid];

    for (int i = tid; i < 3 * 22 * 22; i += 96) {
        int x = i % 22;
        int y = (i / 22) % 22;
        int c = i / 484;
        float v = 0.0f;
        if (y >= 1 && y <= 20 && x >= 1 && x <= 20)
            v = in[c * (IMG_H * IMG_W) + (bh * 20 + y - 1) * IMG_W + (bw * 20 + x - 1)];
        s_in2[c][y][x] = pack2(v);
    }
    __syncthreads();

    #pragma unroll 1
    for (int it = 0; it < 5; it++) {
        const int item = tid + 96 * it;      // 0..479
        const int cg  = item / 80;           // 6 channel groups of 8
        const int rem = item % 80;
        const int p   = rem >> 2;            // row 0..19
        const int q0  = (rem & 3) * 5;       // col group -> 5 cols
        const int oc0 = cg * 8;
        const int c_img = oc0 >> 4;
        const int r1a = (oc0 & 15) >> 2;

        u64 acc[5][4];
        {
            u64 b0 = *(const u64*)&s_b[oc0 + 0];
            u64 b1 = *(const u64*)&s_b[oc0 + 2];
            u64 b2 = *(const u64*)&s_b[oc0 + 4];
            u64 b3 = *(const u64*)&s_b[oc0 + 6];
            #pragma unroll
            for (int j = 0; j < 5; j++) {
                acc[j][0] = b0; acc[j][1] = b1;
                acc[j][2] = b2; acc[j][3] = b3;
            }
        }

        #pragma unroll
        for (int ic = 0; ic < 3; ic++) {
            #pragma unroll
            for (int kh = 0; kh < 3; kh++) {
                u64 xx[7];
                #pragma unroll
                for (int c = 0; c < 7; c++)
                    xx[c] = s_in2[ic][p + kh][q0 + c];
                #pragma unroll
                for (int kw = 0; kw < 3; kw++) {
                    const float* wp = &s_wT[ic * 9 + kh * 3 + kw][oc0];
                    ulonglong2 wA = *(const ulonglong2*)(wp);      // LDS.128: w0,w1
                    ulonglong2 wB = *(const ulonglong2*)(wp + 4);  // LDS.128: w2,w3
                    #pragma unroll
                    for (int j = 0; j < 5; j++) {
                        u64 x = xx[j + kw];
                        acc[j][0] = fma2(x, wA.x, acc[j][0]);
                        acc[j][1] = fma2(x, wA.y, acc[j][1]);
                        acc[j][2] = fma2(x, wB.x, acc[j][2]);
                        acc[j][3] = fma2(x, wB.y, acc[j][3]);
                    }
                }
            }
        }

        #pragma unroll
        for (int j = 0; j < 5; j++) {
            int q = q0 + j;
            size_t base = (size_t)c_img * OUT_PLANE
                        + (size_t)(bh * 80 + p * 4 + r1a) * OUT_W
                        + (bw * 80 + q * 4);
            float4 v;
            unpack2(acc[j][0], v.x, v.y);
            unpack2(acc[j][1], v.z, v.w);
            v.x = fminf(fmaxf(v.x, 0.0f), 0.6f) + 0.4f;
            v.y = fminf(fmaxf(v.y, 0.0f), 0.6f) + 0.4f;
            v.z = fminf(fmaxf(v.z, 0.0f), 0.6f) + 0.4f;
            v.w = fminf(fmaxf(v.w, 0.0f), 0.6f) + 0.4f;
            *reinterpret_cast<float4*>(&out[base]) = v;

            unpack2(acc[j][2], v.x, v.y);
            unpack2(acc[j][3], v.z, v.w);
            v.x = fminf(fmaxf(v.x, 0.0f), 0.6f) + 0.4f;
            v.y = fminf(fmaxf(v.y, 0.0f), 0.6f) + 0.4f;
            v.z = fminf(fmaxf(v.z, 0.0f), 0.6f) + 0.4f;
            v.w = fminf(fmaxf(v.w, 0.0f), 0.6f) + 0.4f;
            *reinterpret_cast<float4*>(&out[base + OUT_W]) = v;
        }
    }
}

// ---------------------------------------------------------------------------
// Kernel A: gate conv1 + maxpool2 + tanh (swapped: tanh monotone) -> g1
// ---------------------------------------------------------------------------
__global__ __launch_bounds__(64)
void gate1_kernel(const float* __restrict__ in,
                  const float* __restrict__ w1,
                  const float* __restrict__ b1)
{
    __shared__ u64  s_in2[3][18][19];
    __shared__ float s_wT[27][16];
    __shared__ float s_b[16];

    const int tid = threadIdx.x;
    const int tx = tid & 7, ty = tid >> 3;
    const int ty0 = blockIdx.y * 8;
    const int tx0 = blockIdx.x * 8;

    for (int i = tid; i < 27 * 16; i += 64) {
        int k = i >> 4, oc = i & 15;
        s_wT[k][oc] = w1[oc * 27 + k];
    }
    if (tid < 16) s_b[tid] = b1[tid];

    for (int i = tid; i < 3 * 18 * 18; i += 64) {
        int x = i % 18;
        int y = (i / 18) % 18;
        int c = i / 324;
        int gy = min(max(ty0 * 2 - 1 + y, 0), IMG_H - 1);
        int gx = min(max(tx0 * 2 - 1 + x, 0), IMG_W - 1);
        s_in2[c][y][x] = pack2(in[c * (IMG_H * IMG_W) + gy * IMG_W + gx]);
    }
    __syncthreads();

    u64 acc[2][2][8];
    {
        #pragma unroll
        for (int m = 0; m < 8; m++) {
            u64 b = *(const u64*)&s_b[2 * m];
            acc[0][0][m] = b; acc[0][1][m] = b;
            acc[1][0][m] = b; acc[1][1][m] = b;
        }
    }

    #pragma unroll
    for (int ic = 0; ic < 3; ic++) {
        #pragma unroll
        for (int kh = 0; kh < 3; kh++) {
            u64 xx[2][4];
            #pragma unroll
            for (int dy = 0; dy < 2; dy++)
                #pragma unroll
                for (int c = 0; c < 4; c++)
                    xx[dy][c] = s_in2[ic][2 * ty + kh + dy][2 * tx + c];
            #pragma unroll
            for (int kw = 0; kw < 3; kw++) {
                const float* wp = &s_wT[ic * 9 + kh * 3 + kw][0];
                u64 w[8];
                #pragma unroll
                for (int m = 0; m < 8; m++) w[m] = *(const u64*)(wp + 2 * m);
                #pragma unroll
                for (int dy = 0; dy < 2; dy++)
                    #pragma unroll
                    for (int dx = 0; dx < 2; dx++) {
                        u64 x = xx[dy][dx + kw];
                        #pragma unroll
                        for (int m = 0; m < 8; m++)
                            acc[dy][dx][m] = fma2(x, w[m], acc[dy][dx][m]);
                    }
            }
        }
    }

    int py = ty0 + ty;
    int px = tx0 + tx;
    if (py < G1_H && px < G1_W) {
        #pragma unroll
        for (int m = 0; m < 8; m++) {
            float m0 = -1e30f, m1 = -1e30f;
            #pragma unroll
            for (int dy = 0; dy < 2; dy++)
                #pragma unroll
                for (int dx = 0; dx < 2; dx++) {
                    float lo, hi;
                    unpack2(acc[dy][dx][m], lo, hi);
                    m0 = fmaxf(m0, lo);
                    m1 = fmaxf(m1, hi);
                }
            g_g1[(2 * m + 0) * G1_AREA + py * G1_W + px] = tanhf(m0);
            g_g1[(2 * m + 1) * G1_AREA + py * G1_W + px] = tanhf(m1);
        }
    }
}

// ---------------------------------------------------------------------------
// Kernel B: gate conv2 + maxpool2 -> g2. 8x8 pooled tile per 64-thread CTA.
// ---------------------------------------------------------------------------
__global__ __launch_bounds__(64)
void gate2_kernel(const float* __restrict__ w2,
                  const float* __restrict__ b2)
{
    __shared__ float s_g[16][18][19];
    __shared__ float s_wT[144][8];

    const int tid = threadIdx.x;
    const int tx = tid & 7, ty = tid >> 3;
    const int ty0 = blockIdx.y * 8;
    const int tx0 = blockIdx.x * 8;

    for (int i = tid; i < 144 * 8; i += 64) {
        int k = i >> 3, oc = i & 7;
        s_wT[k][oc] = w2[oc * 144 + k];
    }

    for (int i = tid; i < 16 * 18 * 18; i += 64) {
        int x = i % 18;
        int y = (i / 18) % 18;
        int c = i / 324;
        int gy = min(max(ty0 * 2 - 1 + y, 0), G1_H - 1);
        int gx = min(max(tx0 * 2 - 1 + x, 0), G1_W - 1);
        s_g[c][y][x] = g_g1[c * G1_AREA + gy * G1_W + gx];
    }
    __syncthreads();

    u64 acc[2][2][4];
    u64 z = pack2(0.0f);
    #pragma unroll
    for (int dy = 0; dy < 2; dy++)
        #pragma unroll
        for (int dx = 0; dx < 2; dx++)
            #pragma unroll
            for (int m = 0; m < 4; m++) acc[dy][dx][m] = z;

    #pragma unroll 1
    for (int ic = 0; ic < 16; ic++) {
        #pragma unroll
        for (int kh = 0; kh < 3; kh++) {
            u64 xx[2][4];
            #pragma unroll
            for (int dy = 0; dy < 2; dy++)
                #pragma unroll
                for (int c = 0; c < 4; c++)
                    xx[dy][c] = pack2(s_g[ic][2 * ty + kh + dy][2 * tx + c]);
            #pragma unroll
            for (int kw = 0; kw < 3; kw++) {
                const float* wp = &s_wT[ic * 9 + kh * 3 + kw][0];
                u64 w0 = *(const u64*)(wp + 0);
                u64 w1 = *(const u64*)(wp + 2);
                u64 w2p = *(const u64*)(wp + 4);
                u64 w3 = *(const u64*)(wp + 6);
                #pragma unroll
                for (int dy = 0; dy < 2; dy++)
                    #pragma unroll
                    for (int dx = 0; dx < 2; dx++) {
                        u64 x = xx[dy][dx + kw];
                        acc[dy][dx][0] = fma2(x, w0, acc[dy][dx][0]);
                        acc[dy][dx][1] = fma2(x, w1, acc[dy][dx][1]);
                        acc[dy][dx][2] = fma2(x, w2p, acc[dy][dx][2]);
                        acc[dy][dx][3] = fma2(x, w3, acc[dy][dx][3]);
                    }
            }
        }
    }

    int py = ty0 + ty;
    int px = tx0 + tx;
    if (py < G2_H && px < G2_W) {
        #pragma unroll
        for (int m = 0; m < 4; m++) {
            float m0 = -1e30f, m1 = -1e30f;
            #pragma unroll
            for (int dy = 0; dy < 2; dy++)
                #pragma unroll
                for (int dx = 0; dx < 2; dx++) {
                    float lo, hi;
                    unpack2(acc[dy][dx][m], lo, hi);
                    m0 = fmaxf(m0, lo);
                    m1 = fmaxf(m1, hi);
                }
            g_g2[(2 * m + 0) * G2_AREA + py * G2_W + px] = m0 + b2[2 * m + 0];
            g_g2[(2 * m + 1) * G2_AREA + py * G2_W + px] = m1 + b2[2 * m + 1];
        }
    }
}

// ---------------------------------------------------------------------------
// Kernel C: gate conv3 (5x5 stride 5) + sigmoid. One warp per output.
// ---------------------------------------------------------------------------
__global__ __launch_bounds__(256)
void gate3_kernel(const float* __restrict__ w3,
                  const float* __restrict__ b3,
                  float* __restrict__ out_cv)
{
    __shared__ float s_w[200];
    int tid = threadIdx.x;
    if (tid < 200) s_w[tid] = w3[tid];
    __syncthreads();

    int lane = tid & 31;
    int o = blockIdx.x * 8 + (tid >> 5);
    if (o >= L_BLOCKS) return;
    int by = o / NW;
    int bx = o % NW;

    float v = 0.0f;
    if (lane < 25) {
        int ky = lane / 5, kx = lane % 5;
        const float* gp = &g_g2[(by * 5 + ky) * G2_W + (bx * 5 + kx)];
        #pragma unroll
        for (int ic = 0; ic < 8; ic++)
            v = fmaf(gp[ic * G2_AREA], s_w[ic * 25 + lane], v);
    }

    v += __shfl_xor_sync(0xffffffffu, v, 16);
    v += __shfl_xor_sync(0xffffffffu, v, 8);
    v += __shfl_xor_sync(0xffffffffu, v, 4);
    v += __shfl_xor_sync(0xffffffffu, v, 2);
    v += __shfl_xor_sync(0xffffffffu, v, 1);

    if (lane == 0)
        out_cv[o] = 1.0f / (1.0f + expf(-(v + b3[0])));
}

// ---------------------------------------------------------------------------
// Launch: LIGHT ENQUEUED FIRST. The work distributor dispatches CTAs in
// launch/capture order; previously the gate branch was enqueued first and
// its 4500+ CTAs drained before light's -> zero overlap despite the fork.
// Dependencies are unchanged: gates depend only on the fork record; the
// main stream joins on the gate branch at the end.
// ---------------------------------------------------------------------------
static cudaStream_t g_sG = 0;
static cudaEvent_t  g_evFork = 0, g_evJoin = 0;

extern "C" void kernel_launch(void* const* d_in, const int* in_sizes, int n_in,
                              void* d_out, int out_size)
{
    const float* in = (const float*)d_in[0];
    const float* w1 = (const float*)d_in[1];
    const float* b1 = (const float*)d_in[2];
    const float* w2 = (const float*)d_in[3];
    const float* b2 = (const float*)d_in[4];
    const float* w3 = (const float*)d_in[5];
    const float* b3 = (const float*)d_in[6];
    const float* wl = (const float*)d_in[7];
    const float* bl = (const float*)d_in[8];
    // complex expert weights (d_in[9..14]) are provably dead: sigmoid(x) > 1 never

    float* out = (float*)d_out;

    if (g_sG == 0) {
        cudaStreamCreateWithFlags(&g_sG, cudaStreamNonBlocking);
        cudaEventCreateWithFlags(&g_evFork, cudaEventDisableTiming);
        cudaEventCreateWithFlags(&g_evJoin, cudaEventDisableTiming);
    }

    // Fork point recorded before any work
    cudaEventRecord(g_evFork, 0);

    // Main stream: light expert FIRST (owns dispatch priority)
    light_kernel<<<L_BLOCKS, 96>>>(in, wl, bl, out);

    // Side stream: gate chain, independent of light, backfills SM gaps
    cudaStreamWaitEvent(g_sG, g_evFork, 0);
    gate1_kernel<<<dim3((G1_W + 7) / 8, (G1_H + 7) / 8), 64, 0, g_sG>>>(in, w1, b1);
    gate2_kernel<<<dim3((G2_W + 7) / 8, (G2_H + 7) / 8), 64, 0, g_sG>>>(w2, b2);
    gate3_kernel<<<L_BLOCKS / 8, 256, 0, g_sG>>>(w3, b3, out + OUT_IMG);
    cudaEventRecord(g_evJoin, g_sG);

    // Join
    cudaStreamWaitEvent(0, g_evJoin, 0);
}